// round 14
// baseline (speedup 1.0000x reference)
#include <cuda_runtime.h>
#include <cstdint>

#define B 8192
#define TC 128                 // tile cols (warp = 32 lanes x float4)
#define TR 256                 // tile rows
#define GX (B / TC)            // 64 col stripes
#define GY (B / TR)            // 32 row bands
#define NBLK (GX * GY)         // 2048

#define NEG_INF __int_as_float(0xff800000)
#define ENC_OFF 0x007FFFFFu    // shifted so enc2(-inf) == 0 (zero-init scratch)

// Final max arrays (zero-init == enc(-inf); finisher resets after reading).
__device__ unsigned g_rowmax[B];         // 32 KB
__device__ unsigned g_colmax[B];         // 32 KB
__device__ float    g_diag[B];
__device__ unsigned g_done;              // zero-init; reset by finisher

// Monotone float<->uint encoding (shifted): atomicMax(unsigned) == float max.
__device__ __forceinline__ unsigned enc2(float f) {
    unsigned u = __float_as_uint(f);
    return (u ^ ((unsigned)((int)u >> 31) | 0x80000000u)) - ENC_OFF;
}
__device__ __forceinline__ float dec2(unsigned e) {
    unsigned x = e + ENC_OFF;
    unsigned u = (x & 0x80000000u) ? (x ^ 0x80000000u) : ~x;
    return __uint_as_float(u);
}

// Warp-wide max via integer REDUX on the monotone encoding (sm_103a-legal).
__device__ __forceinline__ unsigned warp_max_enc(unsigned v) {
    unsigned r;
    asm("redux.sync.max.u32 %0, %1, 0xffffffff;" : "=r"(r) : "r"(v));
    return r;
}

__device__ __forceinline__ void fence_gpu() {
    asm volatile("fence.acq_rel.gpu;" ::: "memory");
}

// ---------------------------------------------------------------------------
// Scan: R12's proven body (REDUX row reduce, plain LDG.128 — no __ldcs).
// Encoded row maxes staged in shared; drain-phase atomics consume directly.
// ---------------------------------------------------------------------------
template<bool DIAG>
__device__ __forceinline__ void scan_body(const float* __restrict__ sim,
                                          int rowBase, int colBase,
                                          int tx, int ty, float* cm,
                                          unsigned* s_row) {
    const int gcol0 = colBase + tx * 4;
    #pragma unroll 4
    for (int r = ty; r < TR; r += 8) {
        const int grow = rowBase + r;
        const float4 v = *reinterpret_cast<const float4*>(
            sim + (size_t)grow * B + gcol0);

        float e0 = v.x, e1 = v.y, e2 = v.z, e3 = v.w;
        if (DIAG) {
            if (grow == gcol0 + 0) { g_diag[grow] = e0; e0 = NEG_INF; }
            if (grow == gcol0 + 1) { g_diag[grow] = e1; e1 = NEG_INF; }
            if (grow == gcol0 + 2) { g_diag[grow] = e2; e2 = NEG_INF; }
            if (grow == gcol0 + 3) { g_diag[grow] = e3; e3 = NEG_INF; }
        }

        cm[0] = fmaxf(cm[0], e0);
        cm[1] = fmaxf(cm[1], e1);
        cm[2] = fmaxf(cm[2], e2);
        cm[3] = fmaxf(cm[3], e3);

        const unsigned rmax_enc =
            warp_max_enc(enc2(fmaxf(fmaxf(e0, e1), fmaxf(e2, e3))));
        if (tx == 0)
            s_row[r] = rmax_enc;           // STS (encoded), not STG
    }
}

__global__ void __launch_bounds__(256) wtl_fused(const float* __restrict__ sim,
                                                 float* __restrict__ out) {
    const int tx = threadIdx.x;            // 0..31
    const int ty = threadIdx.y;            // 0..7
    const int tid = ty * 32 + tx;
    const int colBase = blockIdx.x * TC;
    const int rowBase = blockIdx.y * TR;

    __shared__ unsigned s_row[TR];         // 1 KB (encoded)
    __shared__ float    s_col[8][TC];      // 4 KB

    float cm[4];
    cm[0] = cm[1] = cm[2] = cm[3] = NEG_INF;

    // Diagonal intersects this tile iff bx/2 == by (TC=128, TR=256).
    if ((blockIdx.x >> 1) == blockIdx.y)
        scan_body<true >(sim, rowBase, colBase, tx, ty, cm, s_row);
    else
        scan_body<false>(sim, rowBase, colBase, tx, ty, cm, s_row);

    *reinterpret_cast<float4*>(&s_col[ty][tx * 4]) =
        make_float4(cm[0], cm[1], cm[2], cm[3]);
    __syncthreads();

    // Drain-phase atomics: 256 row + 128 col atomicMax per block.
    atomicMax(&g_rowmax[rowBase + tid], s_row[tid]);   // already encoded

    if (tid < TC) {
        float m = s_col[0][tid];
        #pragma unroll
        for (int s = 1; s < 8; s++) m = fmaxf(m, s_col[s][tid]);
        atomicMax(&g_colmax[colBase + tid], enc2(m));
    }

    // ---- last-block finisher (96 KB, L2-hot; no spin: last arrival means
    //      all 2047 other blocks already released their results) ----
    __shared__ unsigned s_last;
    __syncthreads();
    if (tid == 0) {
        fence_gpu();                       // release this block's work
        s_last = atomicAdd(&g_done, 1u);
    }
    __syncthreads();
    if (s_last != NBLK - 1) return;
    if (tid == 0) fence_gpu();             // acquire everyone's work
    __syncthreads();

    float local = 0.0f;
    #pragma unroll 4
    for (int k = 0; k < B / 256; k++) {    // 32 indices per thread, coalesced
        const int i = k * 256 + tid;
        const float rm  = dec2(__ldcg(&g_rowmax[i]));
        const float cx  = dec2(__ldcg(&g_colmax[i]));
        const float pos = __ldcg(&g_diag[i]);

        g_rowmax[i] = 0u;                  // reset for next graph replay
        g_colmax[i] = 0u;

        const float pos_loss = fmaxf(0.2f * pos * pos - 0.7f * pos + 0.5f, 0.0f);
        if (rm + 1.0f > pos)
            local += pos_loss + fmaxf(0.9f * rm * rm - 0.4f * rm + 0.03f, 0.0f);
        if (cx + 1.0f > pos)
            local += pos_loss + fmaxf(0.9f * cx * cx - 0.4f * cx + 0.03f, 0.0f);
    }

    // deterministic fixed-tree reduction (reuse s_col storage)
    float* s_sum = &s_col[0][0];
    s_sum[tid] = local;
    __syncthreads();
    #pragma unroll
    for (int s = 128; s > 0; s >>= 1) {
        if (tid < s) s_sum[tid] += s_sum[tid + s];
        __syncthreads();
    }
    if (tid == 0) {
        out[0] = s_sum[0] / (float)B;
        g_done = 0u;                       // reset for next replay
    }
}

extern "C" void kernel_launch(void* const* d_in, const int* in_sizes, int n_in,
                              void* d_out, int out_size) {
    const float* sim = (const float*)d_in[0];
    float* out = (float*)d_out;

    dim3 grid(GX, GY);         // (64, 32)
    dim3 block(32, 8);
    wtl_fused<<<grid, block>>>(sim, out);
}

// round 15
// speedup vs baseline: 1.1604x; 1.1604x over previous
#include <cuda_runtime.h>
#include <cstdint>

#define B 8192
#define TC 128                 // tile cols (warp = 32 lanes x float4)
#define TR 256                 // tile rows
#define GX (B / TC)            // 64 col stripes
#define GY (B / TR)            // 32 row bands
#define K2_BLOCKS 64

#define NEG_INF __int_as_float(0xff800000)
#define ENC_OFF 0x007FFFFFu    // shifted so enc2(-inf) == 0 (zero-init scratch)

// Final max arrays (zero-init == enc(-inf); K2 resets them after reading).
__device__ unsigned g_rowmax[B];         // 32 KB
__device__ unsigned g_colmax[B];         // 32 KB
__device__ float    g_diag[B];
__device__ float    g_blocksum[K2_BLOCKS];
__device__ unsigned g_done;              // zero-init; reset by K2 finisher

// Monotone float<->uint encoding (shifted): atomicMax(unsigned) == float max.
__device__ __forceinline__ unsigned enc2(float f) {
    unsigned u = __float_as_uint(f);
    return (u ^ ((unsigned)((int)u >> 31) | 0x80000000u)) - ENC_OFF;
}
__device__ __forceinline__ float dec2(unsigned e) {
    unsigned x = e + ENC_OFF;
    unsigned u = (x & 0x80000000u) ? (x ^ 0x80000000u) : ~x;
    return __uint_as_float(u);
}

// Warp-wide max via integer REDUX on the monotone encoding (sm_103a-legal).
__device__ __forceinline__ unsigned warp_max_enc(unsigned v) {
    unsigned r;
    asm("redux.sync.max.u32 %0, %1, 0xffffffff;" : "=r"(r) : "r"(v));
    return r;
}

// ---------------------------------------------------------------------------
// K1: R12's proven scan — REDUX row reduce, plain LDG.128, drain atomics,
// NO in-kernel fences (kernel boundary is the sync). Unchanged.
// ---------------------------------------------------------------------------
template<bool DIAG>
__device__ __forceinline__ void scan_body(const float* __restrict__ sim,
                                          int rowBase, int colBase,
                                          int tx, int ty, float* cm,
                                          unsigned* s_row) {
    const int gcol0 = colBase + tx * 4;
    #pragma unroll 4
    for (int r = ty; r < TR; r += 8) {
        const int grow = rowBase + r;
        const float4 v = *reinterpret_cast<const float4*>(
            sim + (size_t)grow * B + gcol0);

        float e0 = v.x, e1 = v.y, e2 = v.z, e3 = v.w;
        if (DIAG) {
            if (grow == gcol0 + 0) { g_diag[grow] = e0; e0 = NEG_INF; }
            if (grow == gcol0 + 1) { g_diag[grow] = e1; e1 = NEG_INF; }
            if (grow == gcol0 + 2) { g_diag[grow] = e2; e2 = NEG_INF; }
            if (grow == gcol0 + 3) { g_diag[grow] = e3; e3 = NEG_INF; }
        }

        cm[0] = fmaxf(cm[0], e0);
        cm[1] = fmaxf(cm[1], e1);
        cm[2] = fmaxf(cm[2], e2);
        cm[3] = fmaxf(cm[3], e3);

        const unsigned rmax_enc =
            warp_max_enc(enc2(fmaxf(fmaxf(e0, e1), fmaxf(e2, e3))));
        if (tx == 0)
            s_row[r] = rmax_enc;           // STS (encoded), not STG
    }
}

__global__ void __launch_bounds__(256) wtl_k1(const float* __restrict__ sim) {
    const int tx = threadIdx.x;            // 0..31
    const int ty = threadIdx.y;            // 0..7
    const int tid = ty * 32 + tx;
    const int colBase = blockIdx.x * TC;
    const int rowBase = blockIdx.y * TR;

    __shared__ unsigned s_row[TR];         // 1 KB (encoded)
    __shared__ float    s_col[8][TC];      // 4 KB

    float cm[4];
    cm[0] = cm[1] = cm[2] = cm[3] = NEG_INF;

    // Diagonal intersects this tile iff bx/2 == by (TC=128, TR=256).
    if ((blockIdx.x >> 1) == blockIdx.y)
        scan_body<true >(sim, rowBase, colBase, tx, ty, cm, s_row);
    else
        scan_body<false>(sim, rowBase, colBase, tx, ty, cm, s_row);

    *reinterpret_cast<float4*>(&s_col[ty][tx * 4]) =
        make_float4(cm[0], cm[1], cm[2], cm[3]);
    __syncthreads();

    // Drain-phase atomics: 256 row + 128 col atomicMax per block.
    atomicMax(&g_rowmax[rowBase + tid], s_row[tid]);   // already encoded

    if (tid < TC) {
        float m = s_col[0][tid];
        #pragma unroll
        for (int s = 1; s < 8; s++) m = fmaxf(m, s_col[s][tid]);
        atomicMax(&g_colmax[colBase + tid], enc2(m));
    }
}

// ---------------------------------------------------------------------------
// K2: R10's proven finisher, launched with PDL. The grid prelaunches while
// K1 drains; cudaGridDependencySynchronize() blocks until K1 completes
// (implicit completion => full memory visibility of K1's atomics).
// ---------------------------------------------------------------------------
__global__ void __launch_bounds__(128) wtl_k2(float* __restrict__ out) {
    cudaGridDependencySynchronize();       // wait for K1, visibility guaranteed

    const int tid = threadIdx.x;
    const int i = blockIdx.x * 128 + tid;

    const float rm  = dec2(g_rowmax[i]);
    const float cx  = dec2(g_colmax[i]);
    const float pos = g_diag[i];

    g_rowmax[i] = 0u;                      // reset for next replay
    g_colmax[i] = 0u;

    const float pos_loss = fmaxf(0.2f * pos * pos - 0.7f * pos + 0.5f, 0.0f);
    float local = 0.0f;
    if (rm + 1.0f > pos)
        local += pos_loss + fmaxf(0.9f * rm * rm - 0.4f * rm + 0.03f, 0.0f);
    if (cx + 1.0f > pos)
        local += pos_loss + fmaxf(0.9f * cx * cx - 0.4f * cx + 0.03f, 0.0f);

    // deterministic fixed-tree block reduction
    __shared__ float s_sum[128];
    s_sum[tid] = local;
    __syncthreads();
    #pragma unroll
    for (int s = 64; s > 0; s >>= 1) {
        if (tid < s) s_sum[tid] += s_sum[tid + s];
        __syncthreads();
    }

    // publish; last-arriving block finishes.
    __shared__ unsigned s_last;
    if (tid == 0) {
        g_blocksum[blockIdx.x] = s_sum[0];
        __threadfence();
        s_last = atomicAdd(&g_done, 1u);
    }
    __syncthreads();
    if (s_last != K2_BLOCKS - 1) return;
    if (tid == 0) __threadfence();         // acquire all block sums
    __syncthreads();

    if (tid < 32) {
        float v = g_blocksum[tid] + g_blocksum[tid + 32];  // 64 sums
        #pragma unroll
        for (int o = 16; o > 0; o >>= 1)
            v += __shfl_xor_sync(0xffffffffu, v, o);
        if (tid == 0) {
            out[0] = v / (float)B;
            g_done = 0u;                   // reset for next replay
        }
    }
}

extern "C" void kernel_launch(void* const* d_in, const int* in_sizes, int n_in,
                              void* d_out, int out_size) {
    const float* sim = (const float*)d_in[0];
    float* out = (float*)d_out;

    dim3 grid1(GX, GY);        // (64, 32)
    dim3 block1(32, 8);
    wtl_k1<<<grid1, block1>>>(sim);

    // K2 with programmatic dependent launch: overlap its launch latency
    // with K1's drain.
    cudaLaunchConfig_t cfg = {};
    cfg.gridDim  = dim3(K2_BLOCKS, 1, 1);
    cfg.blockDim = dim3(128, 1, 1);
    cfg.dynamicSmemBytes = 0;
    cudaLaunchAttribute attrs[1];
    attrs[0].id = cudaLaunchAttributeProgrammaticStreamSerialization;
    attrs[0].val.programmaticStreamSerializationAllowed = 1;
    cfg.attrs = attrs;
    cfg.numAttrs = 1;
    cudaLaunchKernelEx(&cfg, wtl_k2, out);
}

// round 16
// speedup vs baseline: 1.1802x; 1.0170x over previous
#include <cuda_runtime.h>
#include <cstdint>

#define B 8192
#define TC 128                 // tile cols (warp = 32 lanes x float4)
#define TR 256                 // tile rows
#define GX (B / TC)            // 64 col stripes
#define GY (B / TR)            // 32 row bands
#define K2_BLOCKS 64

#define NEG_INF __int_as_float(0xff800000)
#define ENC_OFF 0x007FFFFFu    // shifted so enc2(-inf) == 0 (zero-init scratch)

// Final max arrays (zero-init == enc(-inf); K2 resets them after reading).
__device__ unsigned g_rowmax[B];         // 32 KB
__device__ unsigned g_colmax[B];         // 32 KB
__device__ float    g_diag[B];
__device__ float    g_blocksum[K2_BLOCKS];
__device__ unsigned g_done;              // zero-init; reset by K2 finisher

// Monotone float<->uint encoding (shifted): atomicMax(unsigned) == float max.
__device__ __forceinline__ unsigned enc2(float f) {
    unsigned u = __float_as_uint(f);
    return (u ^ ((unsigned)((int)u >> 31) | 0x80000000u)) - ENC_OFF;
}
__device__ __forceinline__ float dec2(unsigned e) {
    unsigned x = e + ENC_OFF;
    unsigned u = (x & 0x80000000u) ? (x ^ 0x80000000u) : ~x;
    return __uint_as_float(u);
}

// Warp-wide max via integer REDUX on the monotone encoding (sm_103a-legal).
__device__ __forceinline__ unsigned warp_max_enc(unsigned v) {
    unsigned r;
    asm("redux.sync.max.u32 %0, %1, 0xffffffff;" : "=r"(r) : "r"(v));
    return r;
}

// ---------------------------------------------------------------------------
// K1: scan with EXPLICIT front-batched loads. redux.sync is a converged
// collective, so ptxas won't hoist the next LDG above it — the old loop ran
// at effective MLP=1. Batch 4 independent LDG.128 first, then reduce.
// Each warp: 8 batches x 4 rows (rows ty+8k within a 32-row group).
// ---------------------------------------------------------------------------
template<bool DIAG>
__device__ __forceinline__ void scan_body(const float* __restrict__ sim,
                                          int rowBase, int colBase,
                                          int tx, int ty, float* cm,
                                          unsigned* s_row) {
    const int gcol0 = colBase + tx * 4;
    #pragma unroll
    for (int bt = 0; bt < TR / 32; bt++) { // 8 batches
        const int r0 = bt * 32 + ty;       // rows r0, r0+8, r0+16, r0+24
        const float* base = sim + (size_t)(rowBase + r0) * B + gcol0;

        float4 v[4];
        #pragma unroll
        for (int k = 0; k < 4; k++)        // 4 independent loads, no sync between
            v[k] = *reinterpret_cast<const float4*>(base + (size_t)k * 8 * B);

        if (DIAG) {
            #pragma unroll
            for (int k = 0; k < 4; k++) {
                const int gr = rowBase + r0 + k * 8;
                if (gr == gcol0 + 0) { g_diag[gr] = v[k].x; v[k].x = NEG_INF; }
                if (gr == gcol0 + 1) { g_diag[gr] = v[k].y; v[k].y = NEG_INF; }
                if (gr == gcol0 + 2) { g_diag[gr] = v[k].z; v[k].z = NEG_INF; }
                if (gr == gcol0 + 3) { g_diag[gr] = v[k].w; v[k].w = NEG_INF; }
            }
        }

        #pragma unroll
        for (int k = 0; k < 4; k++) {
            cm[0] = fmaxf(cm[0], v[k].x);
            cm[1] = fmaxf(cm[1], v[k].y);
            cm[2] = fmaxf(cm[2], v[k].z);
            cm[3] = fmaxf(cm[3], v[k].w);
        }

        #pragma unroll
        for (int k = 0; k < 4; k++) {
            const unsigned rmax_enc = warp_max_enc(
                enc2(fmaxf(fmaxf(v[k].x, v[k].y), fmaxf(v[k].z, v[k].w))));
            if (tx == 0)
                s_row[r0 + k * 8] = rmax_enc;   // STS (encoded)
        }
    }
}

__global__ void __launch_bounds__(256) wtl_k1(const float* __restrict__ sim) {
    const int tx = threadIdx.x;            // 0..31
    const int ty = threadIdx.y;            // 0..7
    const int tid = ty * 32 + tx;
    const int colBase = blockIdx.x * TC;
    const int rowBase = blockIdx.y * TR;

    __shared__ unsigned s_row[TR];         // 1 KB (encoded)
    __shared__ float    s_col[8][TC];      // 4 KB

    float cm[4];
    cm[0] = cm[1] = cm[2] = cm[3] = NEG_INF;

    // Diagonal intersects this tile iff bx/2 == by (TC=128, TR=256).
    if ((blockIdx.x >> 1) == blockIdx.y)
        scan_body<true >(sim, rowBase, colBase, tx, ty, cm, s_row);
    else
        scan_body<false>(sim, rowBase, colBase, tx, ty, cm, s_row);

    *reinterpret_cast<float4*>(&s_col[ty][tx * 4]) =
        make_float4(cm[0], cm[1], cm[2], cm[3]);
    __syncthreads();

    // Drain-phase atomics: 256 row + 128 col atomicMax per block.
    atomicMax(&g_rowmax[rowBase + tid], s_row[tid]);   // already encoded

    if (tid < TC) {
        float m = s_col[0][tid];
        #pragma unroll
        for (int s = 1; s < 8; s++) m = fmaxf(m, s_col[s][tid]);
        atomicMax(&g_colmax[colBase + tid], enc2(m));
    }
}

// ---------------------------------------------------------------------------
// K2: R10's proven finisher, launched with PDL (unchanged from R15 winner).
// ---------------------------------------------------------------------------
__global__ void __launch_bounds__(128) wtl_k2(float* __restrict__ out) {
    cudaGridDependencySynchronize();       // wait for K1, visibility guaranteed

    const int tid = threadIdx.x;
    const int i = blockIdx.x * 128 + tid;

    const float rm  = dec2(g_rowmax[i]);
    const float cx  = dec2(g_colmax[i]);
    const float pos = g_diag[i];

    g_rowmax[i] = 0u;                      // reset for next replay
    g_colmax[i] = 0u;

    const float pos_loss = fmaxf(0.2f * pos * pos - 0.7f * pos + 0.5f, 0.0f);
    float local = 0.0f;
    if (rm + 1.0f > pos)
        local += pos_loss + fmaxf(0.9f * rm * rm - 0.4f * rm + 0.03f, 0.0f);
    if (cx + 1.0f > pos)
        local += pos_loss + fmaxf(0.9f * cx * cx - 0.4f * cx + 0.03f, 0.0f);

    // deterministic fixed-tree block reduction
    __shared__ float s_sum[128];
    s_sum[tid] = local;
    __syncthreads();
    #pragma unroll
    for (int s = 64; s > 0; s >>= 1) {
        if (tid < s) s_sum[tid] += s_sum[tid + s];
        __syncthreads();
    }

    // publish; last-arriving block finishes.
    __shared__ unsigned s_last;
    if (tid == 0) {
        g_blocksum[blockIdx.x] = s_sum[0];
        __threadfence();
        s_last = atomicAdd(&g_done, 1u);
    }
    __syncthreads();
    if (s_last != K2_BLOCKS - 1) return;
    if (tid == 0) __threadfence();         // acquire all block sums
    __syncthreads();

    if (tid < 32) {
        float v = g_blocksum[tid] + g_blocksum[tid + 32];  // 64 sums
        #pragma unroll
        for (int o = 16; o > 0; o >>= 1)
            v += __shfl_xor_sync(0xffffffffu, v, o);
        if (tid == 0) {
            out[0] = v / (float)B;
            g_done = 0u;                   // reset for next replay
        }
    }
}

extern "C" void kernel_launch(void* const* d_in, const int* in_sizes, int n_in,
                              void* d_out, int out_size) {
    const float* sim = (const float*)d_in[0];
    float* out = (float*)d_out;

    dim3 grid1(GX, GY);        // (64, 32)
    dim3 block1(32, 8);
    wtl_k1<<<grid1, block1>>>(sim);

    // K2 with programmatic dependent launch: overlap its launch latency
    // with K1's drain.
    cudaLaunchConfig_t cfg = {};
    cfg.gridDim  = dim3(K2_BLOCKS, 1, 1);
    cfg.blockDim = dim3(128, 1, 1);
    cfg.dynamicSmemBytes = 0;
    cudaLaunchAttribute attrs[1];
    attrs[0].id = cudaLaunchAttributeProgrammaticStreamSerialization;
    attrs[0].val.programmaticStreamSerializationAllowed = 1;
    cfg.attrs = attrs;
    cfg.numAttrs = 1;
    cudaLaunchKernelEx(&cfg, wtl_k2, out);
}